// round 3
// baseline (speedup 1.0000x reference)
#include <cuda_runtime.h>

#define NN 4096
#define DD 512
#define LL 11          // NUM_BINS + 1
#define BM 128
#define BN 128
#define KC 16
#define AST 132        // smem row stride (conflict padding, 16B-aligned)
#define JS 8           // column splits across blocks

__device__ float g_hpos[NN * LL];
__device__ float g_hneg[NN * LL];
__device__ int   g_lab[NN];
__device__ int   g_cnt[64];
__device__ int   g_is32;
__device__ float g_sum;
__device__ float g_nvalid;

// ---------------- K0: zero all accumulators ----------------
__global__ void k_zero() {
    int i = blockIdx.x * blockDim.x + threadIdx.x;
    if (i < NN * LL) { g_hpos[i] = 0.f; g_hneg[i] = 0.f; }
    if (i < 64) g_cnt[i] = 0;
    if (i == 0) { g_is32 = 0; g_sum = 0.f; g_nvalid = 0.f; }
}

// ---------------- K1: detect label dtype (int64 vs silently-demoted int32) ----
// Read only first 2048 int64 views: 16KB, in-bounds for either layout.
__global__ void k_detect(const long long* __restrict__ lab) {
    int i = blockIdx.x * blockDim.x + threadIdx.x;
    if (i < NN / 2) {
        long long v = lab[i];
        if (v < 0 || v > 63) g_is32 = 1;
    }
}

// ---------------- K2: canonicalize labels + per-class counts ----------------
__global__ void k_convert(const long long* __restrict__ lab) {
    int i = blockIdx.x * blockDim.x + threadIdx.x;
    if (i < NN) {
        int v;
        if (g_is32) v = ((const int*)lab)[i];
        else        v = (int)lab[i];
        g_lab[i] = v;
        atomicAdd(&g_cnt[v], 1);
    }
}

// ---------------- K3: fused Gram + soft-histogram ----------------
// Block: rows [bx*128, +128), cols [by*512, +512) in 4 tiles of 128.
// 256 threads, 8x8 microtile as 8x4 f32x2 accumulators.
__global__ __launch_bounds__(256) void k_main(const float* __restrict__ X) {
    extern __shared__ float sm[];
    float* As = sm;                    // [KC][AST] k-major
    float* Bs = As + KC * AST;         // [KC][AST]
    float* sD = Bs + KC * AST;         // [BM][AST] dist tile
    int*   sL = (int*)(sD + BM * AST); // [BN] labels

    const int tid = threadIdx.x;
    const int tr = tid >> 4;           // 0..15 row-thread
    const int tc = tid & 15;           // 0..15 col-thread
    const int row0 = blockIdx.x * BM;
    const int col0 = blockIdx.y * (NN / JS);

    float hp[LL], hn[LL];
    #pragma unroll
    for (int l = 0; l < LL; l++) { hp[l] = 0.f; hn[l] = 0.f; }

    const int myrow = row0 + (tid >> 1);       // hist row owned by this thread
    const int labi  = g_lab[myrow];
    const int chalf = (tid & 1) * 64;          // which 64-col half

    for (int jt = 0; jt < (NN / JS) / BN; jt++) {
        const int c0 = col0 + jt * BN;
        __syncthreads();                       // prev hist done reading sD/sL
        if (tid < BN) sL[tid] = g_lab[c0 + tid];

        unsigned long long acc[8][4];
        #pragma unroll
        for (int m = 0; m < 8; m++)
            #pragma unroll
            for (int n = 0; n < 4; n++) acc[m][n] = 0ull;

        for (int kc = 0; kc < DD; kc += KC) {
            #pragma unroll
            for (int i = 0; i < 2; i++) {
                int t = tid + i * 256;
                int r = t >> 2;
                int kq = (t & 3) * 4;
                float4 va = *(const float4*)&X[(size_t)(row0 + r) * DD + kc + kq];
                As[(kq + 0) * AST + r] = va.x;
                As[(kq + 1) * AST + r] = va.y;
                As[(kq + 2) * AST + r] = va.z;
                As[(kq + 3) * AST + r] = va.w;
                float4 vb = *(const float4*)&X[(size_t)(c0 + r) * DD + kc + kq];
                Bs[(kq + 0) * AST + r] = vb.x;
                Bs[(kq + 1) * AST + r] = vb.y;
                Bs[(kq + 2) * AST + r] = vb.z;
                Bs[(kq + 3) * AST + r] = vb.w;
            }
            __syncthreads();
            #pragma unroll
            for (int k = 0; k < KC; k++) {
                float4 a0 = *(const float4*)&As[k * AST + tr * 8];
                float4 a1 = *(const float4*)&As[k * AST + tr * 8 + 4];
                unsigned long long aa[8];
                asm("mov.b64 %0,{%1,%1};" : "=l"(aa[0]) : "f"(a0.x));
                asm("mov.b64 %0,{%1,%1};" : "=l"(aa[1]) : "f"(a0.y));
                asm("mov.b64 %0,{%1,%1};" : "=l"(aa[2]) : "f"(a0.z));
                asm("mov.b64 %0,{%1,%1};" : "=l"(aa[3]) : "f"(a0.w));
                asm("mov.b64 %0,{%1,%1};" : "=l"(aa[4]) : "f"(a1.x));
                asm("mov.b64 %0,{%1,%1};" : "=l"(aa[5]) : "f"(a1.y));
                asm("mov.b64 %0,{%1,%1};" : "=l"(aa[6]) : "f"(a1.z));
                asm("mov.b64 %0,{%1,%1};" : "=l"(aa[7]) : "f"(a1.w));
                const unsigned long long* bp =
                    (const unsigned long long*)&Bs[k * AST + tc * 8];
                unsigned long long b0 = bp[0], b1 = bp[1], b2 = bp[2], b3 = bp[3];
                #pragma unroll
                for (int m = 0; m < 8; m++) {
                    asm("fma.rn.f32x2 %0,%1,%2,%0;" : "+l"(acc[m][0]) : "l"(aa[m]), "l"(b0));
                    asm("fma.rn.f32x2 %0,%1,%2,%0;" : "+l"(acc[m][1]) : "l"(aa[m]), "l"(b1));
                    asm("fma.rn.f32x2 %0,%1,%2,%0;" : "+l"(acc[m][2]) : "l"(aa[m]), "l"(b2));
                    asm("fma.rn.f32x2 %0,%1,%2,%0;" : "+l"(acc[m][3]) : "l"(aa[m]), "l"(b3));
                }
            }
            __syncthreads();
        }
        // dist2 = 2 - 2*dot -> staged to smem for row-ownership exchange
        #pragma unroll
        for (int m = 0; m < 8; m++) {
            float d[8];
            #pragma unroll
            for (int n = 0; n < 4; n++) {
                unsigned lo, hi;
                asm("mov.b64 {%0,%1},%2;" : "=r"(lo), "=r"(hi) : "l"(acc[m][n]));
                d[2 * n]     = fmaf(__uint_as_float(lo), -2.f, 2.f);
                d[2 * n + 1] = fmaf(__uint_as_float(hi), -2.f, 2.f);
            }
            float* dst = &sD[(tr * 8 + m) * AST + tc * 8];
            *(float4*)dst       = make_float4(d[0], d[1], d[2], d[3]);
            *(float4*)(dst + 4) = make_float4(d[4], d[5], d[6], d[7]);
        }
        __syncthreads();
        // histogram: each thread owns one row-half (64 cols)
        {
            const float* dr = &sD[(tid >> 1) * AST + chalf];
            const int*   lr = &sL[chalf];
            const int dcol = myrow - c0 - chalf; // diagonal position if in [0,64)
            #pragma unroll 4
            for (int c4 = 0; c4 < 16; c4++) {
                float4 dv4 = *(const float4*)&dr[c4 * 4];
                int4   lj4 = *(const int4*)&lr[c4 * 4];
                float dvv[4] = {dv4.x, dv4.y, dv4.z, dv4.w};
                int   ljj[4] = {lj4.x, lj4.y, lj4.z, lj4.w};
                #pragma unroll
                for (int q = 0; q < 4; q++) {
                    int c = c4 * 4 + q;
                    bool same = (ljj[q] == labi);
                    float wp = (same && c != dcol) ? 1.f : 0.f;
                    float wn = same ? 0.f : 1.f;
                    float t = dvv[q] * 2.5f;  // dist2 / delta
                    #pragma unroll
                    for (int l = 0; l < LL; l++) {
                        float p = __saturatef(1.f - fabsf(t - (float)l));
                        hp[l] = fmaf(p, wp, hp[l]);
                        hn[l] = fmaf(p, wn, hn[l]);
                    }
                }
            }
        }
    }
    #pragma unroll
    for (int l = 0; l < LL; l++) {
        atomicAdd(&g_hpos[myrow * LL + l], hp[l]);
        atomicAdd(&g_hneg[myrow * LL + l], hn[l]);
    }
}

// ---------------- K4: per-row AP + reduction ----------------
__global__ void k_rows() {
    int i = blockIdx.x * blockDim.x + threadIdx.x;
    if (i >= NN) return;
    float Np = (float)(g_cnt[g_lab[i]] - 1);
    float Hp = 0.f, Hh = 0.f, rap = 0.f;
    #pragma unroll
    for (int l = 0; l < LL; l++) {
        float hpv = g_hpos[i * LL + l];
        float hnv = g_hneg[i * LL + l];
        Hp += hpv;
        Hh += hpv + hnv;
        if (Hh > 0.f) rap += hpv * Hp / Hh;
    }
    float fa = 0.f, val = 0.f;
    if (Np > 0.f) { fa = rap / Np; val = 1.f; }
    atomicAdd(&g_sum, fa);
    atomicAdd(&g_nvalid, val);
}

// ---------------- K5: final scalar ----------------
__global__ void k_final(float* out) {
    out[0] = 1.f - g_sum / g_nvalid;
}

extern "C" void kernel_launch(void* const* d_in, const int* in_sizes, int n_in,
                              void* d_out, int out_size) {
    const float* X = (const float*)d_in[0];
    const long long* lab = (const long long*)d_in[1];
    float* out = (float*)d_out;

    const size_t SMEM = (size_t)(2 * KC * AST + BM * AST) * sizeof(float)
                        + BN * sizeof(int);
    cudaFuncSetAttribute(k_main, cudaFuncAttributeMaxDynamicSharedMemorySize,
                         (int)SMEM);

    k_zero<<<(NN * LL + 255) / 256, 256>>>();
    k_detect<<<(NN / 2 + 255) / 256, 256>>>(lab);
    k_convert<<<(NN + 255) / 256, 256>>>(lab);
    k_main<<<dim3(NN / BM, JS), 256, SMEM>>>(X);
    k_rows<<<(NN + 255) / 256, 256>>>();
    k_final<<<1, 1>>>(out);
}

// round 4
// speedup vs baseline: 1.0034x; 1.0034x over previous
#include <cuda_runtime.h>

#define NN 4096
#define DD 512
#define LL 11          // NUM_BINS + 1
#define BM 128
#define BN 128
#define KC 16
#define AST 132        // smem row stride (conflict padding, 16B-aligned)
#define JS 8           // column splits across blocks

__device__ float g_hpos[NN * LL];
__device__ float g_hneg[NN * LL];
__device__ int   g_lab[NN];
__device__ int   g_cnt[64];
__device__ int   g_is32;
__device__ float g_sum;
__device__ float g_nvalid;

// ---------------- K0: zero all accumulators ----------------
__global__ void k_zero() {
    int i = blockIdx.x * blockDim.x + threadIdx.x;
    if (i < NN * LL) { g_hpos[i] = 0.f; g_hneg[i] = 0.f; }
    if (i < 64) g_cnt[i] = 0;
    if (i == 0) { g_is32 = 0; g_sum = 0.f; g_nvalid = 0.f; }
}

// ---------------- K1: detect label dtype (int64 vs silently-demoted int32) ----
// Read only first 2048 int64 views: 16KB, in-bounds for either layout.
__global__ void k_detect(const long long* __restrict__ lab) {
    int i = blockIdx.x * blockDim.x + threadIdx.x;
    if (i < NN / 2) {
        long long v = lab[i];
        if (v < 0 || v > 63) g_is32 = 1;
    }
}

// ---------------- K2: canonicalize labels + per-class counts ----------------
__global__ void k_convert(const long long* __restrict__ lab) {
    int i = blockIdx.x * blockDim.x + threadIdx.x;
    if (i < NN) {
        int v;
        if (g_is32) v = ((const int*)lab)[i];
        else        v = (int)lab[i];
        g_lab[i] = v;
        atomicAdd(&g_cnt[v], 1);
    }
}

// ---------------- K3: fused Gram + soft-histogram ----------------
// Block: rows [bx*128, +128), cols [by*512, +512) in 4 tiles of 128.
// 256 threads, 8x8 microtile as 8x4 f32x2 accumulators.
__global__ __launch_bounds__(256) void k_main(const float* __restrict__ X) {
    extern __shared__ float sm[];
    float* As = sm;                    // [KC][AST] k-major
    float* Bs = As + KC * AST;         // [KC][AST]
    float* sD = Bs + KC * AST;         // [BM][AST] dist tile
    int*   sL = (int*)(sD + BM * AST); // [BN] labels

    const int tid = threadIdx.x;
    const int tr = tid >> 4;           // 0..15 row-thread
    const int tc = tid & 15;           // 0..15 col-thread
    const int row0 = blockIdx.x * BM;
    const int col0 = blockIdx.y * (NN / JS);

    float hp[LL], hn[LL];
    #pragma unroll
    for (int l = 0; l < LL; l++) { hp[l] = 0.f; hn[l] = 0.f; }

    const int myrow = row0 + (tid >> 1);       // hist row owned by this thread
    const int labi  = g_lab[myrow];
    const int chalf = (tid & 1) * 64;          // which 64-col half

    for (int jt = 0; jt < (NN / JS) / BN; jt++) {
        const int c0 = col0 + jt * BN;
        __syncthreads();                       // prev hist done reading sD/sL
        if (tid < BN) sL[tid] = g_lab[c0 + tid];

        unsigned long long acc[8][4];
        #pragma unroll
        for (int m = 0; m < 8; m++)
            #pragma unroll
            for (int n = 0; n < 4; n++) acc[m][n] = 0ull;

        for (int kc = 0; kc < DD; kc += KC) {
            #pragma unroll
            for (int i = 0; i < 2; i++) {
                int t = tid + i * 256;
                int r = t >> 2;
                int kq = (t & 3) * 4;
                float4 va = *(const float4*)&X[(size_t)(row0 + r) * DD + kc + kq];
                As[(kq + 0) * AST + r] = va.x;
                As[(kq + 1) * AST + r] = va.y;
                As[(kq + 2) * AST + r] = va.z;
                As[(kq + 3) * AST + r] = va.w;
                float4 vb = *(const float4*)&X[(size_t)(c0 + r) * DD + kc + kq];
                Bs[(kq + 0) * AST + r] = vb.x;
                Bs[(kq + 1) * AST + r] = vb.y;
                Bs[(kq + 2) * AST + r] = vb.z;
                Bs[(kq + 3) * AST + r] = vb.w;
            }
            __syncthreads();
            #pragma unroll
            for (int k = 0; k < KC; k++) {
                float4 a0 = *(const float4*)&As[k * AST + tr * 8];
                float4 a1 = *(const float4*)&As[k * AST + tr * 8 + 4];
                unsigned long long aa[8];
                asm("mov.b64 %0,{%1,%1};" : "=l"(aa[0]) : "f"(a0.x));
                asm("mov.b64 %0,{%1,%1};" : "=l"(aa[1]) : "f"(a0.y));
                asm("mov.b64 %0,{%1,%1};" : "=l"(aa[2]) : "f"(a0.z));
                asm("mov.b64 %0,{%1,%1};" : "=l"(aa[3]) : "f"(a0.w));
                asm("mov.b64 %0,{%1,%1};" : "=l"(aa[4]) : "f"(a1.x));
                asm("mov.b64 %0,{%1,%1};" : "=l"(aa[5]) : "f"(a1.y));
                asm("mov.b64 %0,{%1,%1};" : "=l"(aa[6]) : "f"(a1.z));
                asm("mov.b64 %0,{%1,%1};" : "=l"(aa[7]) : "f"(a1.w));
                const unsigned long long* bp =
                    (const unsigned long long*)&Bs[k * AST + tc * 8];
                unsigned long long b0 = bp[0], b1 = bp[1], b2 = bp[2], b3 = bp[3];
                #pragma unroll
                for (int m = 0; m < 8; m++) {
                    asm("fma.rn.f32x2 %0,%1,%2,%0;" : "+l"(acc[m][0]) : "l"(aa[m]), "l"(b0));
                    asm("fma.rn.f32x2 %0,%1,%2,%0;" : "+l"(acc[m][1]) : "l"(aa[m]), "l"(b1));
                    asm("fma.rn.f32x2 %0,%1,%2,%0;" : "+l"(acc[m][2]) : "l"(aa[m]), "l"(b2));
                    asm("fma.rn.f32x2 %0,%1,%2,%0;" : "+l"(acc[m][3]) : "l"(aa[m]), "l"(b3));
                }
            }
            __syncthreads();
        }
        // dist2 = 2 - 2*dot -> staged to smem for row-ownership exchange
        #pragma unroll
        for (int m = 0; m < 8; m++) {
            float d[8];
            #pragma unroll
            for (int n = 0; n < 4; n++) {
                unsigned lo, hi;
                asm("mov.b64 {%0,%1},%2;" : "=r"(lo), "=r"(hi) : "l"(acc[m][n]));
                d[2 * n]     = fmaf(__uint_as_float(lo), -2.f, 2.f);
                d[2 * n + 1] = fmaf(__uint_as_float(hi), -2.f, 2.f);
            }
            float* dst = &sD[(tr * 8 + m) * AST + tc * 8];
            *(float4*)dst       = make_float4(d[0], d[1], d[2], d[3]);
            *(float4*)(dst + 4) = make_float4(d[4], d[5], d[6], d[7]);
        }
        __syncthreads();
        // histogram: each thread owns one row-half (64 cols)
        {
            const float* dr = &sD[(tid >> 1) * AST + chalf];
            const int*   lr = &sL[chalf];
            const int dcol = myrow - c0 - chalf; // diagonal position if in [0,64)
            #pragma unroll 4
            for (int c4 = 0; c4 < 16; c4++) {
                float4 dv4 = *(const float4*)&dr[c4 * 4];
                int4   lj4 = *(const int4*)&lr[c4 * 4];
                float dvv[4] = {dv4.x, dv4.y, dv4.z, dv4.w};
                int   ljj[4] = {lj4.x, lj4.y, lj4.z, lj4.w};
                #pragma unroll
                for (int q = 0; q < 4; q++) {
                    int c = c4 * 4 + q;
                    bool same = (ljj[q] == labi);
                    float wp = (same && c != dcol) ? 1.f : 0.f;
                    float wn = same ? 0.f : 1.f;
                    float t = dvv[q] * 2.5f;  // dist2 / delta
                    #pragma unroll
                    for (int l = 0; l < LL; l++) {
                        float p = __saturatef(1.f - fabsf(t - (float)l));
                        hp[l] = fmaf(p, wp, hp[l]);
                        hn[l] = fmaf(p, wn, hn[l]);
                    }
                }
            }
        }
    }
    #pragma unroll
    for (int l = 0; l < LL; l++) {
        atomicAdd(&g_hpos[myrow * LL + l], hp[l]);
        atomicAdd(&g_hneg[myrow * LL + l], hn[l]);
    }
}

// ---------------- K4: per-row AP + reduction ----------------
__global__ void k_rows() {
    int i = blockIdx.x * blockDim.x + threadIdx.x;
    if (i >= NN) return;
    float Np = (float)(g_cnt[g_lab[i]] - 1);
    float Hp = 0.f, Hh = 0.f, rap = 0.f;
    #pragma unroll
    for (int l = 0; l < LL; l++) {
        float hpv = g_hpos[i * LL + l];
        float hnv = g_hneg[i * LL + l];
        Hp += hpv;
        Hh += hpv + hnv;
        if (Hh > 0.f) rap += hpv * Hp / Hh;
    }
    float fa = 0.f, val = 0.f;
    if (Np > 0.f) { fa = rap / Np; val = 1.f; }
    atomicAdd(&g_sum, fa);
    atomicAdd(&g_nvalid, val);
}

// ---------------- K5: final scalar ----------------
__global__ void k_final(float* out) {
    out[0] = 1.f - g_sum / g_nvalid;
}

extern "C" void kernel_launch(void* const* d_in, const int* in_sizes, int n_in,
                              void* d_out, int out_size) {
    const float* X = (const float*)d_in[0];
    const long long* lab = (const long long*)d_in[1];
    float* out = (float*)d_out;

    const size_t SMEM = (size_t)(2 * KC * AST + BM * AST) * sizeof(float)
                        + BN * sizeof(int);
    cudaFuncSetAttribute(k_main, cudaFuncAttributeMaxDynamicSharedMemorySize,
                         (int)SMEM);

    k_zero<<<(NN * LL + 255) / 256, 256>>>();
    k_detect<<<(NN / 2 + 255) / 256, 256>>>(lab);
    k_convert<<<(NN + 255) / 256, 256>>>(lab);
    k_main<<<dim3(NN / BM, JS), 256, SMEM>>>(X);
    k_rows<<<(NN + 255) / 256, 256>>>();
    k_final<<<1, 1>>>(out);
}